// round 1
// baseline (speedup 1.0000x reference)
#include <cuda_runtime.h>
#include <math.h>

#define NN 100000
#define NE 1600000
#define DH 128
#define DO 64

// ---------------- device scratch (static; no allocation allowed) ----------------
__device__ int   g_deg[NN];
__device__ int   g_fill[NN];
__device__ int   g_rowptr[NN];
__device__ int   g_csr[NE];
__device__ float g_dinv[NN];
__device__ float g_z[(size_t)NN * DH];
__device__ float g_h[(size_t)NN * DH];
__device__ float g_wt[DH * DH];
__device__ int   g_bsums[128];

// ---------------- prep kernels ----------------
__global__ void k_zero() {
    int i = blockIdx.x * 256 + threadIdx.x;
    if (i < NN) { g_deg[i] = 0; g_fill[i] = 0; }
}

__global__ void k_hist(const int* __restrict__ dst) {
    int i = blockIdx.x * 256 + threadIdx.x;
    if (i < NE) atomicAdd(&g_deg[dst[i]], 1);
}

__global__ void k_dinv() {
    int i = blockIdx.x * 256 + threadIdx.x;
    if (i < NN) g_dinv[i] = rsqrtf((float)(g_deg[i] + 1));  // +1 self loop
}

// exclusive scan of g_deg -> g_rowptr (3-phase)
__global__ void k_scan1() {
    __shared__ int s[1024];
    int t = threadIdx.x;
    int i = blockIdx.x * 1024 + t;
    int val = (i < NN) ? g_deg[i] : 0;
    s[t] = val;
    __syncthreads();
    for (int off = 1; off < 1024; off <<= 1) {
        int x = (t >= off) ? s[t - off] : 0;
        __syncthreads();
        if (t >= off) s[t] += x;
        __syncthreads();
    }
    if (i < NN) g_rowptr[i] = s[t] - val;        // exclusive
    if (t == 1023) g_bsums[blockIdx.x] = s[1023];
}

__global__ void k_scan2(int nb) {
    int run = 0;
    for (int b = 0; b < nb; b++) { int v = g_bsums[b]; g_bsums[b] = run; run += v; }
}

__global__ void k_scan3() {
    int i = blockIdx.x * 1024 + threadIdx.x;
    if (i < NN) g_rowptr[i] += g_bsums[blockIdx.x];
}

__global__ void k_csr(const int* __restrict__ src, const int* __restrict__ dst) {
    int i = blockIdx.x * 256 + threadIdx.x;
    if (i < NE) {
        int d = dst[i];
        int pos = g_rowptr[d] + atomicAdd(&g_fill[d], 1);
        g_csr[pos] = src[i];
    }
}

// transpose W [DH x outc] -> g_wt [outc x DH] so GEMM reads K contiguously
__global__ void k_transpose(const float* __restrict__ W, int outc) {
    int i = blockIdx.x * 256 + threadIdx.x;
    if (i < DH * outc) {
        int k = i / outc, t = i - k * outc;
        g_wt[t * DH + k] = W[i];
    }
}

// ---------------- GEMM: Z[v][t] = dinv[v] * dot(X[v,:], W[:,t]) ----------------
// block = OUTC threads, handles 8 nodes. Wt row per thread (float4 over K),
// X rows staged in smem (broadcast reads, conflict-free).
template <int OUTC>
__global__ void k_gemm(const float* __restrict__ X, float* __restrict__ Z) {
    __shared__ float xs[8][DH];
    int t = threadIdx.x;
    int base = blockIdx.x * 8;  // NN divisible by 8
    for (int i = t; i < 8 * DH; i += OUTC) {
        int j = i >> 7, k = i & 127;
        xs[j][k] = X[(size_t)(base + j) * DH + k];
    }
    __syncthreads();
    float acc[8] = {0.f, 0.f, 0.f, 0.f, 0.f, 0.f, 0.f, 0.f};
    const float* w = g_wt + t * DH;
#pragma unroll
    for (int k = 0; k < DH; k += 4) {
        float4 w4 = *(const float4*)(w + k);
#pragma unroll
        for (int j = 0; j < 8; j++) {
            float4 x4 = *(const float4*)(&xs[j][k]);
            acc[j] = fmaf(x4.x, w4.x, fmaf(x4.y, w4.y, fmaf(x4.z, w4.z, fmaf(x4.w, w4.w, acc[j]))));
        }
    }
#pragma unroll
    for (int j = 0; j < 8; j++) {
        int v = base + j;
        Z[(size_t)v * OUTC + t] = g_dinv[v] * acc[j];
    }
}

// ---------------- aggregation: H[v] = act(dinv[v]*(sum_nbr z[src] + z[v]) + b) ----------------
template <int VPT>
__device__ __forceinline__ void addrow(float* acc, const float* __restrict__ Z, int s, int lane) {
    const float* p = Z + (size_t)s * (VPT * 32) + lane * VPT;
    if (VPT == 4) {
        float4 x = *(const float4*)p;
        acc[0] += x.x; acc[1] += x.y; acc[2] += x.z; acc[3] += x.w;
    } else {
        float2 x = *(const float2*)p;
        acc[0] += x.x; acc[1] += x.y;
    }
}

template <int OUTC, bool RELU, bool LSM>
__global__ void k_agg(const float* __restrict__ Z, const float* __restrict__ bias,
                      float* __restrict__ out) {
    int v = (blockIdx.x * blockDim.x + threadIdx.x) >> 5;  // uniform across warp
    if (v >= NN) return;
    int lane = threadIdx.x & 31;
    constexpr int VPT = OUTC / 32;
    float acc[VPT];

    // self term z[v]
    {
        const float* p = Z + (size_t)v * OUTC + lane * VPT;
        if (VPT == 4) {
            float4 x = *(const float4*)p;
            acc[0] = x.x; acc[1] = x.y; acc[2] = x.z; acc[3] = x.w;
        } else {
            float2 x = *(const float2*)p;
            acc[0] = x.x; acc[1] = x.y;
        }
    }

    int start = g_rowptr[v];
    int cnt = g_deg[v];
    int e = 0;
    for (; e + 4 <= cnt; e += 4) {  // 4 independent gathers in flight
        int s0 = g_csr[start + e + 0];
        int s1 = g_csr[start + e + 1];
        int s2 = g_csr[start + e + 2];
        int s3 = g_csr[start + e + 3];
        addrow<VPT>(acc, Z, s0, lane);
        addrow<VPT>(acc, Z, s1, lane);
        addrow<VPT>(acc, Z, s2, lane);
        addrow<VPT>(acc, Z, s3, lane);
    }
    for (; e < cnt; e++) addrow<VPT>(acc, Z, g_csr[start + e], lane);

    float dv = g_dinv[v];
    float h[VPT];
#pragma unroll
    for (int i = 0; i < VPT; i++) {
        h[i] = fmaf(dv, acc[i], bias[lane * VPT + i]);
        if (RELU) h[i] = fmaxf(h[i], 0.f);
    }

    if (LSM) {
        float m = h[0];
#pragma unroll
        for (int i = 1; i < VPT; i++) m = fmaxf(m, h[i]);
#pragma unroll
        for (int off = 16; off > 0; off >>= 1)
            m = fmaxf(m, __shfl_xor_sync(0xffffffffu, m, off));
        float s = 0.f;
#pragma unroll
        for (int i = 0; i < VPT; i++) s += expf(h[i] - m);
#pragma unroll
        for (int off = 16; off > 0; off >>= 1)
            s += __shfl_xor_sync(0xffffffffu, s, off);
        float l = m + logf(s);
#pragma unroll
        for (int i = 0; i < VPT; i++) h[i] -= l;
    }

    float* op = out + (size_t)v * OUTC + lane * VPT;
    if (VPT == 4) {
        *(float4*)op = make_float4(h[0], h[1], h[2], h[3]);
    } else {
        *(float2*)op = make_float2(h[0], h[1]);
    }
}

// ---------------- launch ----------------
extern "C" void kernel_launch(void* const* d_in, const int* in_sizes, int n_in,
                              void* d_out, int out_size) {
    const int*   edges = (const int*)d_in[0];
    const int*   esrc  = edges;        // edges[0,:]
    const int*   edst  = edges + NE;   // edges[1,:]
    const float* X  = (const float*)d_in[1];
    const float* W0 = (const float*)d_in[2];
    const float* b0 = (const float*)d_in[3];
    const float* W1 = (const float*)d_in[4];
    const float* b1 = (const float*)d_in[5];
    const float* W2 = (const float*)d_in[6];
    const float* b2 = (const float*)d_in[7];
    float* out = (float*)d_out;

    float *zp, *hp;
    cudaGetSymbolAddress((void**)&zp, g_z);
    cudaGetSymbolAddress((void**)&hp, g_h);

    const int scan_blocks = (NN + 1023) / 1024;   // 98

    // --- graph prep ---
    k_zero<<<(NN + 255) / 256, 256>>>();
    k_hist<<<(NE + 255) / 256, 256>>>(edst);
    k_dinv<<<(NN + 255) / 256, 256>>>();
    k_scan1<<<scan_blocks, 1024>>>();
    k_scan2<<<1, 1>>>(scan_blocks);
    k_scan3<<<scan_blocks, 1024>>>();
    k_csr<<<(NE + 255) / 256, 256>>>(esrc, edst);

    const int gemm_blocks = NN / 8;     // 12500
    const int agg_blocks  = NN / 8;     // 256 thr = 8 warps/block

    // --- layer 1 ---
    k_transpose<<<(DH * DH + 255) / 256, 256>>>(W0, DH);
    k_gemm<DH><<<gemm_blocks, DH>>>(X, zp);
    k_agg<DH, true, false><<<agg_blocks, 256>>>(zp, b0, hp);

    // --- layer 2 ---
    k_transpose<<<(DH * DH + 255) / 256, 256>>>(W1, DH);
    k_gemm<DH><<<gemm_blocks, DH>>>(hp, zp);
    k_agg<DH, true, false><<<agg_blocks, 256>>>(zp, b1, hp);

    // --- layer 3 + log_softmax ---
    k_transpose<<<(DH * DO + 255) / 256, 256>>>(W2, DO);
    k_gemm<DO><<<gemm_blocks, DO>>>(hp, zp);
    k_agg<DO, false, true><<<agg_blocks, 256>>>(zp, b2, out);
}

// round 3
// speedup vs baseline: 2.1388x; 2.1388x over previous
#include <cuda_runtime.h>
#include <cuda_bf16.h>
#include <math.h>
#include <stdint.h>

#define NN 100000
#define NE 1600000
#define DH 128
#define DO 64

// ---------------- device scratch (static; no allocation allowed) ----------------
__device__ int   g_deg[NN];
__device__ int   g_fill[NN];
__device__ int   g_rowptr[NN];
__device__ int   g_csr[NE];
__device__ float g_dinv[NN];
__device__ float g_z[(size_t)NN * DH];
__device__ float g_h[(size_t)NN * DH];
__device__ int   g_bsums[128];
// weights packed as bf16x2 (hi/lo split), layout [col][kpair] stride 68 words
__device__ uint32_t g_wbh[128 * 68];
__device__ uint32_t g_wbl[128 * 68];

// ---------------- bf16 split helpers ----------------
__device__ __forceinline__ void split2(float x, float y, uint32_t& hp, uint32_t& lp) {
    __nv_bfloat16 hx = __float2bfloat16(x);
    __nv_bfloat16 hy = __float2bfloat16(y);
    __nv_bfloat16 lx = __float2bfloat16(x - __bfloat162float(hx));
    __nv_bfloat16 ly = __float2bfloat16(y - __bfloat162float(hy));
    hp = ((uint32_t)__bfloat16_as_ushort(hy) << 16) | (uint32_t)__bfloat16_as_ushort(hx);
    lp = ((uint32_t)__bfloat16_as_ushort(ly) << 16) | (uint32_t)__bfloat16_as_ushort(lx);
}

__device__ __forceinline__ void mma_bf16(float* c, const uint32_t* a, uint32_t b0, uint32_t b1) {
    asm volatile(
        "mma.sync.aligned.m16n8k16.row.col.f32.bf16.bf16.f32 "
        "{%0,%1,%2,%3}, {%4,%5,%6,%7}, {%8,%9}, {%0,%1,%2,%3};"
        : "+f"(c[0]), "+f"(c[1]), "+f"(c[2]), "+f"(c[3])
        : "r"(a[0]), "r"(a[1]), "r"(a[2]), "r"(a[3]), "r"(b0), "r"(b1));
}

// ---------------- prep kernels ----------------
__global__ void k_zero() {
    int i = blockIdx.x * 256 + threadIdx.x;
    if (i < NN) { g_deg[i] = 0; g_fill[i] = 0; }
}
__global__ void k_hist(const int* __restrict__ dst) {
    int i = blockIdx.x * 256 + threadIdx.x;
    if (i < NE) atomicAdd(&g_deg[dst[i]], 1);
}
__global__ void k_dinv() {
    int i = blockIdx.x * 256 + threadIdx.x;
    if (i < NN) g_dinv[i] = rsqrtf((float)(g_deg[i] + 1));
}
__global__ void k_scan1() {
    __shared__ int s[1024];
    int t = threadIdx.x;
    int i = blockIdx.x * 1024 + t;
    int val = (i < NN) ? g_deg[i] : 0;
    s[t] = val;
    __syncthreads();
    for (int off = 1; off < 1024; off <<= 1) {
        int x = (t >= off) ? s[t - off] : 0;
        __syncthreads();
        if (t >= off) s[t] += x;
        __syncthreads();
    }
    if (i < NN) g_rowptr[i] = s[t] - val;
    if (t == 1023) g_bsums[blockIdx.x] = s[1023];
}
__global__ void k_scan2(int nb) {
    int run = 0;
    for (int b = 0; b < nb; b++) { int v = g_bsums[b]; g_bsums[b] = run; run += v; }
}
__global__ void k_scan3() {
    int i = blockIdx.x * 1024 + threadIdx.x;
    if (i < NN) g_rowptr[i] += g_bsums[blockIdx.x];
}
__global__ void k_csr(const int* __restrict__ src, const int* __restrict__ dst) {
    int i = blockIdx.x * 256 + threadIdx.x;
    if (i < NE) {
        int d = dst[i];
        int pos = g_rowptr[d] + atomicAdd(&g_fill[d], 1);
        g_csr[pos] = src[i];
    }
}

// ---------------- weight conversion: W[k][col] fp32 -> bf16x2 hi/lo, [col][kpair] stride 68 ----------------
__global__ void k_wconv(const float* __restrict__ W, int outc) {
    int i = blockIdx.x * 256 + threadIdx.x;
    if (i >= outc * 64) return;
    int col = i >> 6;
    int kp  = i & 63;
    float w0 = W[(2 * kp) * outc + col];
    float w1 = W[(2 * kp + 1) * outc + col];
    uint32_t hp, lp;
    split2(w0, w1, hp, lp);
    g_wbh[col * 68 + kp] = hp;
    g_wbl[col * 68 + kp] = lp;
}

// ---------------- mma.sync GEMM: Z[v][t] = dinv[v] * dot(X[v,:], W[:,t]) ----------------
// Block: 256 threads (8 warps), M-tile 128, warp computes rows wid*16..+15 x OUTC.
// Split precision: D = Ah*Bh + Ah*Bl + Al*Bh (fp32 accum). Stride-68 banking:
// 68 % 32 == 4 makes each fragment load (8 rows x 4 kp) hit 32 distinct banks.
template <int OUTC>
__global__ void __launch_bounds__(256, 1) k_gemm(const float* __restrict__ X,
                                                 float* __restrict__ Z) {
    extern __shared__ uint32_t sm[];
    uint32_t* Ash = sm;                    // 128*68
    uint32_t* Asl = Ash + 128 * 68;
    uint32_t* Bsh = Asl + 128 * 68;        // OUTC*68
    uint32_t* Bsl = Bsh + OUTC * 68;
    int tid = threadIdx.x;
    int base = blockIdx.x * 128;

    // stage B (pre-packed global -> smem verbatim)
    for (int i = tid; i < OUTC * 68; i += 256) {
        Bsh[i] = g_wbh[i];
        Bsl[i] = g_wbl[i];
    }

    // stage A: convert fp32 row -> bf16 hi/lo pairs
    {
        int row = tid >> 1, half = tid & 1;
        int v = base + row;
        uint32_t* dh = Ash + row * 68 + half * 32;
        uint32_t* dl = Asl + row * 68 + half * 32;
        if (v < NN) {
            const float4* xr = (const float4*)(X + (size_t)v * DH + half * 64);
#pragma unroll
            for (int i = 0; i < 16; i++) {
                float4 x = xr[i];
                uint32_t ph0, pl0, ph1, pl1;
                split2(x.x, x.y, ph0, pl0);
                split2(x.z, x.w, ph1, pl1);
                *(uint2*)(dh + i * 2) = make_uint2(ph0, ph1);
                *(uint2*)(dl + i * 2) = make_uint2(pl0, pl1);
            }
        } else {
#pragma unroll
            for (int i = 0; i < 16; i++) {
                *(uint2*)(dh + i * 2) = make_uint2(0u, 0u);
                *(uint2*)(dl + i * 2) = make_uint2(0u, 0u);
            }
        }
    }
    __syncthreads();

    int wid = tid >> 5, lane = tid & 31;
    int gp = lane >> 2, qp = lane & 3;
    int r0 = wid * 16 + gp;

    float acc[OUTC / 8][4];
#pragma unroll
    for (int j = 0; j < OUTC / 8; j++) {
        acc[j][0] = 0.f; acc[j][1] = 0.f; acc[j][2] = 0.f; acc[j][3] = 0.f;
    }

#pragma unroll
    for (int ks = 0; ks < 8; ks++) {
        int ak = ks * 8 + qp;
        uint32_t ah[4], al[4];
        ah[0] = Ash[r0 * 68 + ak];
        ah[1] = Ash[(r0 + 8) * 68 + ak];
        ah[2] = Ash[r0 * 68 + ak + 4];
        ah[3] = Ash[(r0 + 8) * 68 + ak + 4];
        al[0] = Asl[r0 * 68 + ak];
        al[1] = Asl[(r0 + 8) * 68 + ak];
        al[2] = Asl[r0 * 68 + ak + 4];
        al[3] = Asl[(r0 + 8) * 68 + ak + 4];
#pragma unroll
        for (int j = 0; j < OUTC / 8; j++) {
            int c = (j * 8 + gp) * 68 + ak;
            uint32_t bh0 = Bsh[c], bh1 = Bsh[c + 4];
            uint32_t bl0 = Bsl[c], bl1 = Bsl[c + 4];
            mma_bf16(acc[j], ah, bh0, bh1);
            mma_bf16(acc[j], ah, bl0, bl1);
            mma_bf16(acc[j], al, bh0, bh1);
        }
    }

    // epilogue: scale by dinv, store fp32
    int v0 = base + r0;
    int v8 = v0 + 8;
    float d0 = (v0 < NN) ? g_dinv[v0] : 0.f;
    float d8 = (v8 < NN) ? g_dinv[v8] : 0.f;
#pragma unroll
    for (int j = 0; j < OUTC / 8; j++) {
        int col = j * 8 + qp * 2;
        if (v0 < NN)
            *(float2*)(Z + (size_t)v0 * OUTC + col) = make_float2(d0 * acc[j][0], d0 * acc[j][1]);
        if (v8 < NN)
            *(float2*)(Z + (size_t)v8 * OUTC + col) = make_float2(d8 * acc[j][2], d8 * acc[j][3]);
    }
}

// ---------------- aggregation (unchanged from R1) ----------------
template <int VPT>
__device__ __forceinline__ void addrow(float* acc, const float* __restrict__ Z, int s, int lane) {
    const float* p = Z + (size_t)s * (VPT * 32) + lane * VPT;
    if (VPT == 4) {
        float4 x = *(const float4*)p;
        acc[0] += x.x; acc[1] += x.y; acc[2] += x.z; acc[3] += x.w;
    } else {
        float2 x = *(const float2*)p;
        acc[0] += x.x; acc[1] += x.y;
    }
}

template <int OUTC, bool RELU, bool LSM>
__global__ void k_agg(const float* __restrict__ Z, const float* __restrict__ bias,
                      float* __restrict__ out) {
    int v = (blockIdx.x * blockDim.x + threadIdx.x) >> 5;
    if (v >= NN) return;
    int lane = threadIdx.x & 31;
    constexpr int VPT = OUTC / 32;
    float acc[VPT];
    {
        const float* p = Z + (size_t)v * OUTC + lane * VPT;
        if (VPT == 4) {
            float4 x = *(const float4*)p;
            acc[0] = x.x; acc[1] = x.y; acc[2] = x.z; acc[3] = x.w;
        } else {
            float2 x = *(const float2*)p;
            acc[0] = x.x; acc[1] = x.y;
        }
    }
    int start = g_rowptr[v];
    int cnt = g_deg[v];
    int e = 0;
    for (; e + 4 <= cnt; e += 4) {
        int s0 = g_csr[start + e + 0];
        int s1 = g_csr[start + e + 1];
        int s2 = g_csr[start + e + 2];
        int s3 = g_csr[start + e + 3];
        addrow<VPT>(acc, Z, s0, lane);
        addrow<VPT>(acc, Z, s1, lane);
        addrow<VPT>(acc, Z, s2, lane);
        addrow<VPT>(acc, Z, s3, lane);
    }
    for (; e < cnt; e++) addrow<VPT>(acc, Z, g_csr[start + e], lane);

    float dv = g_dinv[v];
    float h[VPT];
#pragma unroll
    for (int i = 0; i < VPT; i++) {
        h[i] = fmaf(dv, acc[i], bias[lane * VPT + i]);
        if (RELU) h[i] = fmaxf(h[i], 0.f);
    }
    if (LSM) {
        float m = h[0];
#pragma unroll
        for (int i = 1; i < VPT; i++) m = fmaxf(m, h[i]);
#pragma unroll
        for (int off = 16; off > 0; off >>= 1)
            m = fmaxf(m, __shfl_xor_sync(0xffffffffu, m, off));
        float s = 0.f;
#pragma unroll
        for (int i = 0; i < VPT; i++) s += expf(h[i] - m);
#pragma unroll
        for (int off = 16; off > 0; off >>= 1)
            s += __shfl_xor_sync(0xffffffffu, s, off);
        float l = m + logf(s);
#pragma unroll
        for (int i = 0; i < VPT; i++) h[i] -= l;
    }
    float* op = out + (size_t)v * OUTC + lane * VPT;
    if (VPT == 4) {
        *(float4*)op = make_float4(h[0], h[1], h[2], h[3]);
    } else {
        *(float2*)op = make_float2(h[0], h[1]);
    }
}

// ---------------- launch ----------------
extern "C" void kernel_launch(void* const* d_in, const int* in_sizes, int n_in,
                              void* d_out, int out_size) {
    const int*   edges = (const int*)d_in[0];
    const int*   esrc  = edges;
    const int*   edst  = edges + NE;
    const float* X  = (const float*)d_in[1];
    const float* W0 = (const float*)d_in[2];
    const float* b0 = (const float*)d_in[3];
    const float* W1 = (const float*)d_in[4];
    const float* b1 = (const float*)d_in[5];
    const float* W2 = (const float*)d_in[6];
    const float* b2 = (const float*)d_in[7];
    float* out = (float*)d_out;

    float *zp, *hp;
    cudaGetSymbolAddress((void**)&zp, g_z);
    cudaGetSymbolAddress((void**)&hp, g_h);

    const int SMEM_G128 = (128 * 68 * 2 + DH * 68 * 2) * 4;  // 139264
    const int SMEM_G64  = (128 * 68 * 2 + DO * 68 * 2) * 4;  // 104448
    cudaFuncSetAttribute(k_gemm<DH>, cudaFuncAttributeMaxDynamicSharedMemorySize, SMEM_G128);
    cudaFuncSetAttribute(k_gemm<DO>, cudaFuncAttributeMaxDynamicSharedMemorySize, SMEM_G64);

    const int scan_blocks = (NN + 1023) / 1024;

    // --- graph prep ---
    k_zero<<<(NN + 255) / 256, 256>>>();
    k_hist<<<(NE + 255) / 256, 256>>>(edst);
    k_dinv<<<(NN + 255) / 256, 256>>>();
    k_scan1<<<scan_blocks, 1024>>>();
    k_scan2<<<1, 1>>>(scan_blocks);
    k_scan3<<<scan_blocks, 1024>>>();
    k_csr<<<(NE + 255) / 256, 256>>>(esrc, edst);

    const int gemm_blocks = (NN + 127) / 128;  // 782
    const int agg_blocks  = NN / 8;

    // --- layer 1 ---
    k_wconv<<<(DH * 64 + 255) / 256, 256>>>(W0, DH);
    k_gemm<DH><<<gemm_blocks, 256, SMEM_G128>>>(X, zp);
    k_agg<DH, true, false><<<agg_blocks, 256>>>(zp, b0, hp);

    // --- layer 2 ---
    k_wconv<<<(DH * 64 + 255) / 256, 256>>>(W1, DH);
    k_gemm<DH><<<gemm_blocks, 256, SMEM_G128>>>(hp, zp);
    k_agg<DH, true, false><<<agg_blocks, 256>>>(zp, b1, hp);

    // --- layer 3 + log_softmax ---
    k_wconv<<<(DO * 64 + 255) / 256, 256>>>(W2, DO);
    k_gemm<DO><<<gemm_blocks, 256, SMEM_G64>>>(hp, zp);
    k_agg<DO, false, true><<<agg_blocks, 256>>>(zp, b2, out);
}

// round 5
// speedup vs baseline: 2.3105x; 1.0803x over previous
#include <cuda_runtime.h>
#include <cuda_bf16.h>
#include <cuda_fp16.h>
#include <math.h>
#include <stdint.h>

#define NN 100000
#define NE 1600000
#define DH 128
#define DO 64

// ---------------- device scratch (static; no allocation allowed) ----------------
__device__ int    g_deg[NN];
__device__ int    g_fill[NN];
__device__ int    g_rowptr[NN];
__device__ int    g_csr[NE];
__device__ float  g_dinv[NN];
__device__ __half g_z[(size_t)NN * DH];   // post-GEMM activations (fp16)
__device__ float  g_h[(size_t)NN * DH];   // post-agg activations (fp32)
__device__ int    g_bsums[128];

// ---------------- bf16 split helpers ----------------
__device__ __forceinline__ void split2(float x, float y, uint32_t& hp, uint32_t& lp) {
    __nv_bfloat16 hx = __float2bfloat16(x);
    __nv_bfloat16 hy = __float2bfloat16(y);
    __nv_bfloat16 lx = __float2bfloat16(x - __bfloat162float(hx));
    __nv_bfloat16 ly = __float2bfloat16(y - __bfloat162float(hy));
    hp = ((uint32_t)__bfloat16_as_ushort(hy) << 16) | (uint32_t)__bfloat16_as_ushort(hx);
    lp = ((uint32_t)__bfloat16_as_ushort(ly) << 16) | (uint32_t)__bfloat16_as_ushort(lx);
}

__device__ __forceinline__ void mma_bf16(float* c, const uint32_t* a, uint32_t b0, uint32_t b1) {
    asm volatile(
        "mma.sync.aligned.m16n8k16.row.col.f32.bf16.bf16.f32 "
        "{%0,%1,%2,%3}, {%4,%5,%6,%7}, {%8,%9}, {%0,%1,%2,%3};"
        : "+f"(c[0]), "+f"(c[1]), "+f"(c[2]), "+f"(c[3])
        : "r"(a[0]), "r"(a[1]), "r"(a[2]), "r"(a[3]), "r"(b0), "r"(b1));
}

// ---------------- prep kernels ----------------
__global__ void k_zero() {
    int i = blockIdx.x * 256 + threadIdx.x;
    if (i < NN) { g_deg[i] = 0; g_fill[i] = 0; }
}
__global__ void k_hist(const int* __restrict__ dst) {
    int i = blockIdx.x * 256 + threadIdx.x;
    if (i < NE) atomicAdd(&g_deg[dst[i]], 1);
}
// scan phase 1, fused with dinv computation
__global__ void k_scan1() {
    __shared__ int s[1024];
    int t = threadIdx.x;
    int i = blockIdx.x * 1024 + t;
    int val = (i < NN) ? g_deg[i] : 0;
    if (i < NN) g_dinv[i] = rsqrtf((float)val + 1.0f);  // +1 self loop
    s[t] = val;
    __syncthreads();
    for (int off = 1; off < 1024; off <<= 1) {
        int x = (t >= off) ? s[t - off] : 0;
        __syncthreads();
        if (t >= off) s[t] += x;
        __syncthreads();
    }
    if (i < NN) g_rowptr[i] = s[t] - val;
    if (t == 1023) g_bsums[blockIdx.x] = s[1023];
}
// block-parallel scan of the 98 block sums (was single-threaded serial)
__global__ void k_scan2(int nb) {
    __shared__ int s[128];
    int t = threadIdx.x;
    int v = (t < nb) ? g_bsums[t] : 0;
    s[t] = v;
    __syncthreads();
    for (int off = 1; off < 128; off <<= 1) {
        int x = (t >= off) ? s[t - off] : 0;
        __syncthreads();
        if (t >= off) s[t] += x;
        __syncthreads();
    }
    if (t < nb) g_bsums[t] = s[t] - v;  // exclusive
}
__global__ void k_scan3() {
    int i = blockIdx.x * 1024 + threadIdx.x;
    if (i < NN) g_rowptr[i] += g_bsums[blockIdx.x];
}
__global__ void k_csr(const int* __restrict__ src, const int* __restrict__ dst) {
    int i = blockIdx.x * 256 + threadIdx.x;
    if (i < NE) {
        int d = dst[i];
        int pos = g_rowptr[d] + atomicAdd(&g_fill[d], 1);
        g_csr[pos] = src[i];
    }
}

// ---------------- mma.sync GEMM: Z[v][t] = dinv[v] * dot(X[v,:], W[:,t]) ----------------
// Block: 256 threads (8 warps), M-tile 128, warp computes rows wid*16..+15 x OUTC.
// Split precision: D = Ah*Bh + Ah*Bl + Al*Bh (fp32 accum). Stride-68 banking:
// 68 % 32 == 4 keeps fragment loads conflict-free.
// W conversion (fp32 -> bf16 hi/lo, [col][kpair]) is done in-block from global W.
// Output Z is written as fp16 (half2) to halve downstream gather traffic.
template <int OUTC>
__global__ void __launch_bounds__(256, 1) k_gemm(const float* __restrict__ X,
                                                 const float* __restrict__ W,
                                                 __half* __restrict__ Z) {
    extern __shared__ uint32_t sm[];
    uint32_t* Ash = sm;                    // 128*68
    uint32_t* Asl = Ash + 128 * 68;
    uint32_t* Bsh = Asl + 128 * 68;        // OUTC*68
    uint32_t* Bsl = Bsh + OUTC * 68;
    int tid = threadIdx.x;
    int base = blockIdx.x * 128;

    // stage B: coalesced fp32 reads of W [DH x OUTC], bf16 hi/lo 16-bit smem stores
    {
        uint16_t* bh16 = (uint16_t*)Bsh;
        uint16_t* bl16 = (uint16_t*)Bsl;
        for (int i = tid; i < DH * OUTC; i += 256) {
            int k = i / OUTC, col = i - k * OUTC;   // consecutive tid -> consecutive col
            float w = W[i];
            __nv_bfloat16 h = __float2bfloat16(w);
            __nv_bfloat16 l = __float2bfloat16(w - __bfloat162float(h));
            int idx = (col * 68 + (k >> 1)) * 2 + (k & 1);
            bh16[idx] = __bfloat16_as_ushort(h);
            bl16[idx] = __bfloat16_as_ushort(l);
        }
    }

    // stage A: convert fp32 row -> bf16 hi/lo pairs
    {
        int row = tid >> 1, half = tid & 1;
        int v = base + row;
        uint32_t* dh = Ash + row * 68 + half * 32;
        uint32_t* dl = Asl + row * 68 + half * 32;
        if (v < NN) {
            const float4* xr = (const float4*)(X + (size_t)v * DH + half * 64);
#pragma unroll
            for (int i = 0; i < 16; i++) {
                float4 x = xr[i];
                uint32_t ph0, pl0, ph1, pl1;
                split2(x.x, x.y, ph0, pl0);
                split2(x.z, x.w, ph1, pl1);
                *(uint2*)(dh + i * 2) = make_uint2(ph0, ph1);
                *(uint2*)(dl + i * 2) = make_uint2(pl0, pl1);
            }
        } else {
#pragma unroll
            for (int i = 0; i < 16; i++) {
                *(uint2*)(dh + i * 2) = make_uint2(0u, 0u);
                *(uint2*)(dl + i * 2) = make_uint2(0u, 0u);
            }
        }
    }
    __syncthreads();

    int wid = tid >> 5, lane = tid & 31;
    int gp = lane >> 2, qp = lane & 3;
    int r0 = wid * 16 + gp;

    float acc[OUTC / 8][4];
#pragma unroll
    for (int j = 0; j < OUTC / 8; j++) {
        acc[j][0] = 0.f; acc[j][1] = 0.f; acc[j][2] = 0.f; acc[j][3] = 0.f;
    }

#pragma unroll
    for (int ks = 0; ks < 8; ks++) {
        int ak = ks * 8 + qp;
        uint32_t ah[4], al[4];
        ah[0] = Ash[r0 * 68 + ak];
        ah[1] = Ash[(r0 + 8) * 68 + ak];
        ah[2] = Ash[r0 * 68 + ak + 4];
        ah[3] = Ash[(r0 + 8) * 68 + ak + 4];
        al[0] = Asl[r0 * 68 + ak];
        al[1] = Asl[(r0 + 8) * 68 + ak];
        al[2] = Asl[r0 * 68 + ak + 4];
        al[3] = Asl[(r0 + 8) * 68 + ak + 4];
#pragma unroll
        for (int j = 0; j < OUTC / 8; j++) {
            int c = (j * 8 + gp) * 68 + ak;
            uint32_t bh0 = Bsh[c], bh1 = Bsh[c + 4];
            uint32_t bl0 = Bsl[c], bl1 = Bsl[c + 4];
            mma_bf16(acc[j], ah, bh0, bh1);
            mma_bf16(acc[j], ah, bl0, bl1);
            mma_bf16(acc[j], al, bh0, bh1);
        }
    }

    // epilogue: scale by dinv, store fp16 (half2 per j per row)
    int v0 = base + r0;
    int v8 = v0 + 8;
    float d0 = (v0 < NN) ? g_dinv[v0] : 0.f;
    float d8 = (v8 < NN) ? g_dinv[v8] : 0.f;
#pragma unroll
    for (int j = 0; j < OUTC / 8; j++) {
        int col = j * 8 + qp * 2;
        if (v0 < NN)
            *(__half2*)(Z + (size_t)v0 * OUTC + col) =
                __float22half2_rn(make_float2(d0 * acc[j][0], d0 * acc[j][1]));
        if (v8 < NN)
            *(__half2*)(Z + (size_t)v8 * OUTC + col) =
                __float22half2_rn(make_float2(d8 * acc[j][2], d8 * acc[j][3]));
    }
}

// ---------------- aggregation: out[v] = act(dinv[v]*(sum_nbr z[src] + z[v]) + b) ----------------
// Z is fp16. VPT = OUTC/32 halfs per lane (4 for DH: one uint2; 2 for DO: one uint).
template <int VPT>
__device__ __forceinline__ void ld_row(uint32_t* r, const __half* __restrict__ Z,
                                       int s, int lane) {
    const char* p = (const char*)(Z) + ((size_t)s * (VPT * 32) + lane * VPT) * 2;
    if (VPT == 4) {
        uint2 x = *(const uint2*)p;
        r[0] = x.x; r[1] = x.y;
    } else {
        r[0] = *(const uint32_t*)p;
    }
}
template <int VPT>
__device__ __forceinline__ void acc_row(float* acc, const uint32_t* r) {
#pragma unroll
    for (int q = 0; q < VPT / 2; q++) {
        float2 f = __half22float2(*(const __half2*)&r[q]);
        acc[2 * q] += f.x;
        acc[2 * q + 1] += f.y;
    }
}

template <int OUTC, bool RELU, bool LSM>
__global__ void k_agg(const __half* __restrict__ Z, const float* __restrict__ bias,
                      float* __restrict__ out) {
    int v = (blockIdx.x * blockDim.x + threadIdx.x) >> 5;
    if (v >= NN) return;
    int lane = threadIdx.x & 31;
    constexpr int VPT = OUTC / 32;
    float acc[VPT];
#pragma unroll
    for (int i = 0; i < VPT; i++) acc[i] = 0.f;

    // self term
    {
        uint32_t r[VPT / 2];
        ld_row<VPT>(r, Z, v, lane);
        acc_row<VPT>(acc, r);
    }

    int start = g_rowptr[v];
    int cnt = g_deg[v];
    int e = 0;
    for (; e + 4 <= cnt; e += 4) {
        int s0 = g_csr[start + e + 0];
        int s1 = g_csr[start + e + 1];
        int s2 = g_csr[start + e + 2];
        int s3 = g_csr[start + e + 3];
        uint32_t r0[VPT / 2], r1[VPT / 2], r2[VPT / 2], r3[VPT / 2];
        ld_row<VPT>(r0, Z, s0, lane);   // 4 independent gathers in flight
        ld_row<VPT>(r1, Z, s1, lane);
        ld_row<VPT>(r2, Z, s2, lane);
        ld_row<VPT>(r3, Z, s3, lane);
        acc_row<VPT>(acc, r0);
        acc_row<VPT>(acc, r1);
        acc_row<VPT>(acc, r2);
        acc_row<VPT>(acc, r3);
    }
    for (; e < cnt; e++) {
        uint32_t r[VPT / 2];
        ld_row<VPT>(r, Z, g_csr[start + e], lane);
        acc_row<VPT>(acc, r);
    }

    float dv = g_dinv[v];
    float h[VPT];
#pragma unroll
    for (int i = 0; i < VPT; i++) {
        h[i] = fmaf(dv, acc[i], bias[lane * VPT + i]);
        if (RELU) h[i] = fmaxf(h[i], 0.f);
    }
    if (LSM) {
        float m = h[0];
#pragma unroll
        for (int i = 1; i < VPT; i++) m = fmaxf(m, h[i]);
#pragma unroll
        for (int off = 16; off > 0; off >>= 1)
            m = fmaxf(m, __shfl_xor_sync(0xffffffffu, m, off));
        float s = 0.f;
#pragma unroll
        for (int i = 0; i < VPT; i++) s += expf(h[i] - m);
#pragma unroll
        for (int off = 16; off > 0; off >>= 1)
            s += __shfl_xor_sync(0xffffffffu, s, off);
        float l = m + logf(s);
#pragma unroll
        for (int i = 0; i < VPT; i++) h[i] -= l;
    }
    float* op = out + (size_t)v * OUTC + lane * VPT;
    if (VPT == 4) {
        *(float4*)op = make_float4(h[0], h[1], h[2], h[3]);
    } else {
        *(float2*)op = make_float2(h[0], h[1]);
    }
}

// ---------------- launch ----------------
extern "C" void kernel_launch(void* const* d_in, const int* in_sizes, int n_in,
                              void* d_out, int out_size) {
    const int*   edges = (const int*)d_in[0];
    const int*   esrc  = edges;
    const int*   edst  = edges + NE;
    const float* X  = (const float*)d_in[1];
    const float* W0 = (const float*)d_in[2];
    const float* b0 = (const float*)d_in[3];
    const float* W1 = (const float*)d_in[4];
    const float* b1 = (const float*)d_in[5];
    const float* W2 = (const float*)d_in[6];
    const float* b2 = (const float*)d_in[7];
    float* out = (float*)d_out;

    __half* zp;
    float*  hp;
    cudaGetSymbolAddress((void**)&zp, g_z);
    cudaGetSymbolAddress((void**)&hp, g_h);

    const int SMEM_G128 = (128 * 68 * 2 + DH * 68 * 2) * 4;  // 139264
    const int SMEM_G64  = (128 * 68 * 2 + DO * 68 * 2) * 4;  // 104448
    cudaFuncSetAttribute(k_gemm<DH>, cudaFuncAttributeMaxDynamicSharedMemorySize, SMEM_G128);
    cudaFuncSetAttribute(k_gemm<DO>, cudaFuncAttributeMaxDynamicSharedMemorySize, SMEM_G64);

    const int scan_blocks = (NN + 1023) / 1024;   // 98

    // --- graph prep ---
    k_zero<<<(NN + 255) / 256, 256>>>();
    k_hist<<<(NE + 255) / 256, 256>>>(edst);
    k_scan1<<<scan_blocks, 1024>>>();
    k_scan2<<<1, 128>>>(scan_blocks);
    k_scan3<<<scan_blocks, 1024>>>();
    k_csr<<<(NE + 255) / 256, 256>>>(esrc, edst);

    const int gemm_blocks = (NN + 127) / 128;  // 782
    const int agg_blocks  = NN / 8;

    // --- layer 1 ---
    k_gemm<DH><<<gemm_blocks, 256, SMEM_G128>>>(X, W0, zp);
    k_agg<DH, true, false><<<agg_blocks, 256>>>(zp, b0, hp);

    // --- layer 2 ---
    k_gemm<DH><<<gemm_blocks, 256, SMEM_G128>>>(hp, W1, zp);
    k_agg<DH, true, false><<<agg_blocks, 256>>>(zp, b1, hp);

    // --- layer 3 + log_softmax ---
    k_gemm<DO><<<gemm_blocks, 256, SMEM_G64>>>(hp, W2, zp);
    k_agg<DO, false, true><<<agg_blocks, 256>>>(zp, b2, out);
}